// round 1
// baseline (speedup 1.0000x reference)
#include <cuda_runtime.h>

#define DIMS   120
#define NPIX   14400        // 120*120
#define SS2    81
#define C32    32
#define B64    64
#define PITCH  84           // 81 padded to multiple of 4, zeros in [81..83]
#define V4PIX  841          // 29*29
#define FLATN  13456        // 16*841

// Intermediates (allocation-free scratch)
__device__ float g_cplx[8 * NPIX * B64];   // [s][pix][b]
__device__ float g_v4[B64 * FLATN];        // [b][o*841 + pix]

// ---------------------------------------------------------------------------
// Kernel 1: V1 locally-connected layer + relu + phase-mean, fused.
// One block per output pixel. 64x32x81 GEMM with per-pixel weights.
// ---------------------------------------------------------------------------
__global__ __launch_bounds__(128, 4)
void v1_kernel(const float* __restrict__ x, const float* __restrict__ w)
{
    int p = blockIdx.x;                 // 0..14399
    int i = p / DIMS;
    int j = p - i * DIMS;

    __shared__ __align__(16) float w_s[C32][PITCH];   // [c][k]
    __shared__ __align__(16) float p_s[B64][PITCH];   // [b][k]

    int t = threadIdx.x;

    // --- load per-pixel weights (coalesced in 81-float runs per channel) ---
    const float* wp = w + p * SS2;
    for (int idx = t; idx < C32 * SS2; idx += 128) {
        int c = idx / SS2;
        int k = idx - c * SS2;
        w_s[c][k] = wp[c * (NPIX * SS2) + k];
    }
    // --- load patches: p_s[b][k] = x[b, i + k/9, j + k%9] ---
    const float* xp = x + i * 128 + j;
    for (int idx = t; idx < B64 * SS2; idx += 128) {
        int b = idx / SS2;
        int k = idx - b * SS2;
        int r = k / 9;
        int q = k - r * 9;
        p_s[b][k] = xp[b * 16384 + r * 128 + q];
    }
    // zero the K padding so the last k-quad is harmless
    if (t < 96) {
        if (t < 32) { w_s[t][81] = 0.f; w_s[t][82] = 0.f; w_s[t][83] = 0.f; }
        else { int b = t - 32; p_s[b][81] = 0.f; p_s[b][82] = 0.f; p_s[b][83] = 0.f; }
    }
    __syncthreads();

    // --- register-tiled GEMM: thread = 4 batches x 4 channels ---
    int tx = t & 7;          // channel group == orientation s (4 phases each)
    int ty = t >> 3;         // batch group
    int c0 = tx * 4;
    int b0 = ty * 4;

    float acc[4][4];
#pragma unroll
    for (int bi = 0; bi < 4; bi++)
#pragma unroll
        for (int ci = 0; ci < 4; ci++) acc[bi][ci] = 0.f;

#pragma unroll 7
    for (int kq = 0; kq < 21; kq++) {
        float4 wv[4], pv[4];
#pragma unroll
        for (int ci = 0; ci < 4; ci++)
            wv[ci] = *(const float4*)&w_s[c0 + ci][kq * 4];
#pragma unroll
        for (int bi = 0; bi < 4; bi++)
            pv[bi] = *(const float4*)&p_s[b0 + bi][kq * 4];
#pragma unroll
        for (int bi = 0; bi < 4; bi++)
#pragma unroll
            for (int ci = 0; ci < 4; ci++) {
                acc[bi][ci] += pv[bi].x * wv[ci].x;
                acc[bi][ci] += pv[bi].y * wv[ci].y;
                acc[bi][ci] += pv[bi].z * wv[ci].z;
                acc[bi][ci] += pv[bi].w * wv[ci].w;
            }
    }

    // --- relu + mean over the 4 phases of orientation tx ---
    float* cp = g_cplx + tx * (NPIX * B64) + p * B64 + b0;
#pragma unroll
    for (int bi = 0; bi < 4; bi++) {
        float ssum = fmaxf(acc[bi][0], 0.f) + fmaxf(acc[bi][1], 0.f)
                   + fmaxf(acc[bi][2], 0.f) + fmaxf(acc[bi][3], 0.f);
        cp[bi] = ssum * 0.25f;
    }
}

// ---------------------------------------------------------------------------
// Kernel 2: V4 locally-connected pooling. One block per V4 pixel.
// out[b,o] = sum_{s,pos} cplx[s][pix2(pos)][b] * vw[o][s][pix][pos]
// ---------------------------------------------------------------------------
__global__ __launch_bounds__(128, 8)
void v4_kernel(const float* __restrict__ vw)
{
    int p = blockIdx.x;                 // 0..840
    int ii = p / 29;
    int jj = p - ii * 29;
    int base_pix = (ii * 4) * DIMS + jj * 4;

    __shared__ __align__(16) float w_s[64][16];   // [k][o]
    __shared__ __align__(16) float p_s[64][64];   // [pos][b]

    int t = threadIdx.x;
    int to = t & 7;          // o0 = to*2
    int tb = t >> 3;         // b0 = tb*4
    int o0 = to * 2;
    int b0 = tb * 4;

    float acc[4][2];
#pragma unroll
    for (int bi = 0; bi < 4; bi++) { acc[bi][0] = 0.f; acc[bi][1] = 0.f; }

    for (int s = 0; s < 8; s++) {
        __syncthreads();
        // weights: vw[(((o*8)+s)*841 + p)*64 + k], store transposed [k][o]
        for (int f = t; f < 256; f += 128) {
            int o = f >> 4, kq = f & 15;
            float4 v = *(const float4*)&vw[((((o << 3) + s) * V4PIX) + p) * 64 + kq * 4];
            w_s[kq * 4 + 0][o] = v.x;
            w_s[kq * 4 + 1][o] = v.y;
            w_s[kq * 4 + 2][o] = v.z;
            w_s[kq * 4 + 3][o] = v.w;
        }
        // patch: cplx[s][base_pix + di*120 + dj][b], 64 consecutive floats per pos
        const float* cb = g_cplx + s * (NPIX * B64);
        for (int f = t; f < 1024; f += 128) {
            int pos = f >> 4, bq = f & 15;
            int di = pos >> 3, dj = pos & 7;
            float4 v = *(const float4*)&cb[(base_pix + di * DIMS + dj) * B64 + bq * 4];
            *(float4*)&p_s[pos][bq * 4] = v;
        }
        __syncthreads();

#pragma unroll
        for (int k = 0; k < 64; k++) {
            float4 pv = *(const float4*)&p_s[k][b0];
            float2 wv = *(const float2*)&w_s[k][o0];
            acc[0][0] += pv.x * wv.x;  acc[0][1] += pv.x * wv.y;
            acc[1][0] += pv.y * wv.x;  acc[1][1] += pv.y * wv.y;
            acc[2][0] += pv.z * wv.x;  acc[2][1] += pv.z * wv.y;
            acc[3][0] += pv.w * wv.x;  acc[3][1] += pv.w * wv.y;
        }
    }

#pragma unroll
    for (int bi = 0; bi < 4; bi++)
#pragma unroll
        for (int oi = 0; oi < 2; oi++)
            g_v4[(b0 + bi) * FLATN + (o0 + oi) * V4PIX + p] = acc[bi][oi];
}

// ---------------------------------------------------------------------------
// Kernel 3: decision readout. One block per batch element; deterministic
// fixed-order tree reduction (no float atomics).
// ---------------------------------------------------------------------------
__global__ __launch_bounds__(256)
void dec_kernel(const float* __restrict__ dw, const float* __restrict__ db,
                float* __restrict__ out)
{
    int b = blockIdx.x;
    int t = threadIdx.x;
    const float* v = g_v4 + b * FLATN;

    float a0 = 0.f, a1 = 0.f;
    for (int idx = t; idx < FLATN; idx += 256) {
        float vv = v[idx];
        a0 += vv * dw[idx];
        a1 += vv * dw[FLATN + idx];
    }

    __shared__ float s0[256], s1[256];
    s0[t] = a0; s1[t] = a1;
    __syncthreads();
    for (int off = 128; off > 0; off >>= 1) {
        if (t < off) { s0[t] += s0[t + off]; s1[t] += s1[t + off]; }
        __syncthreads();
    }
    if (t == 0) {
        out[b * 2 + 0] = s0[0] + db[0];
        out[b * 2 + 1] = s1[0] + db[1];
    }
}

// ---------------------------------------------------------------------------
extern "C" void kernel_launch(void* const* d_in, const int* in_sizes, int n_in,
                              void* d_out, int out_size)
{
    const float* x  = (const float*)d_in[0];   // [64,1,128,128]
    const float* sw = (const float*)d_in[1];   // [32,120,120,81]
    const float* vw = (const float*)d_in[2];   // [16,8,29,29,64]
    const float* dw = (const float*)d_in[3];   // [2,13456]
    const float* db = (const float*)d_in[4];   // [2]
    float* out = (float*)d_out;                // [64,2]

    v1_kernel<<<NPIX, 128>>>(x, sw);
    v4_kernel<<<V4PIX, 128>>>(vw);
    dec_kernel<<<B64, 256>>>(dw, db, out);
}

// round 2
// speedup vs baseline: 1.2092x; 1.2092x over previous
#include <cuda_runtime.h>

#define DIMS   120
#define NPIX   14400        // 120*120
#define SS2    81
#define C32    32
#define B64    64
#define PITCH  84           // 81 padded to 84 floats (21 quads); cols 81..83 zeroed
#define V4PIX  841          // 29*29
#define FLATN  13456        // 16*841

// Intermediates (allocation-free scratch)
__device__ float g_cplx[8 * NPIX * B64];   // [s][pix][b]
__device__ float g_v4[B64 * FLATN];        // [b][o*841 + pix]

// packed fp32x2 FMA: d.lo += a.lo*b.lo, d.hi += a.hi*b.hi  (2x fp32 rate on sm_103a)
__device__ __forceinline__ void fma_x2(unsigned long long& d,
                                       unsigned long long a,
                                       unsigned long long b) {
    asm volatile("fma.rn.f32x2 %0, %1, %2, %0;" : "+l"(d) : "l"(a), "l"(b));
}
__device__ __forceinline__ float hsum_x2(unsigned long long v) {
    float2 f = *reinterpret_cast<float2*>(&v);
    return f.x + f.y;
}

// ---------------------------------------------------------------------------
// Kernel 1: V1 locally-connected layer + relu + phase-mean, fused.
// One block per output pixel: a 64x32x81 GEMM with per-pixel weights.
// Thread (tx,ty): tx in 0..7 = orientation, ty in 0..15 = batch group.
// Channel c stored at smem row (c>>2)+8*(c&3) -> thread tx reads rows
// tx+8*ci (bank-disjoint). Batch b stored at row b; thread reads ty+16*bi
// (bank-disjoint). Dot products accumulate in fp32x2 lanes (even/odd k).
// ---------------------------------------------------------------------------
__global__ __launch_bounds__(128, 4)
void v1_kernel(const float* __restrict__ x, const float* __restrict__ w)
{
    int p = blockIdx.x;                 // 0..14399
    int i = p / DIMS;
    int j = p - i * DIMS;

    __shared__ __align__(16) float w_s[C32][PITCH];   // permuted rows
    __shared__ __align__(16) float p_s[B64][PITCH];   // row = batch

    int t = threadIdx.x;

    // --- stage per-pixel weights, permuting channel -> row ---
    const float* wp = w + p * SS2;
    for (int idx = t; idx < C32 * SS2; idx += 128) {
        int c = idx / SS2;
        int k = idx - c * SS2;
        int row = (c >> 2) + ((c & 3) << 3);
        w_s[row][k] = wp[c * (NPIX * SS2) + k];
    }
    // --- stage patches: p_s[b][k] = x[b, i + k/9, j + k%9] ---
    const float* xp = x + i * 128 + j;
    for (int idx = t; idx < B64 * SS2; idx += 128) {
        int b = idx / SS2;
        int k = idx - b * SS2;
        int r = k / 9;
        int q = k - r * 9;
        p_s[b][k] = xp[b * 16384 + r * 128 + q];
    }
    // zero K padding (cols 81..83) so the last k-quad is harmless
    if (t < 96) {
        if (t < 32) { w_s[t][81] = 0.f; w_s[t][82] = 0.f; w_s[t][83] = 0.f; }
        else { int b = t - 32; p_s[b][81] = 0.f; p_s[b][82] = 0.f; p_s[b][83] = 0.f; }
    }
    __syncthreads();

    int tx = t & 7;          // orientation s
    int ty = t >> 3;         // batch group

    unsigned long long acc[4][4];   // [bi][ci], fp32x2 lanes = (k even, k odd)
#pragma unroll
    for (int bi = 0; bi < 4; bi++)
#pragma unroll
        for (int ci = 0; ci < 4; ci++) acc[bi][ci] = 0ull;

#pragma unroll 7
    for (int kq = 0; kq < 21; kq++) {
        ulonglong2 wv[4], pv[4];
#pragma unroll
        for (int ci = 0; ci < 4; ci++)
            wv[ci] = *(const ulonglong2*)&w_s[tx + (ci << 3)][kq * 4];
#pragma unroll
        for (int bi = 0; bi < 4; bi++)
            pv[bi] = *(const ulonglong2*)&p_s[ty + (bi << 4)][kq * 4];
#pragma unroll
        for (int bi = 0; bi < 4; bi++)
#pragma unroll
            for (int ci = 0; ci < 4; ci++) {
                fma_x2(acc[bi][ci], pv[bi].x, wv[ci].x);
                fma_x2(acc[bi][ci], pv[bi].y, wv[ci].y);
            }
    }

    // --- relu + mean over the 4 phases of orientation tx ---
    float* cp = g_cplx + tx * (NPIX * B64) + p * B64;
#pragma unroll
    for (int bi = 0; bi < 4; bi++) {
        float s0 = fmaxf(hsum_x2(acc[bi][0]), 0.f);
        float s1 = fmaxf(hsum_x2(acc[bi][1]), 0.f);
        float s2 = fmaxf(hsum_x2(acc[bi][2]), 0.f);
        float s3 = fmaxf(hsum_x2(acc[bi][3]), 0.f);
        cp[ty + (bi << 4)] = (s0 + s1 + s2 + s3) * 0.25f;
    }
}

// ---------------------------------------------------------------------------
// Kernel 2: V4 locally-connected pooling. One block per V4 pixel.
// out[b,o] = sum_{s,pos} cplx[s][pix2(pos)][b] * vw[o][s][pix][pos]
// fp32x2 lanes = adjacent batch pair; weight operand pre-duplicated in smem.
// ---------------------------------------------------------------------------
__global__ __launch_bounds__(128, 8)
void v4_kernel(const float* __restrict__ vw)
{
    int p = blockIdx.x;                 // 0..840
    int ii = p / 29;
    int jj = p - ii * 29;
    int base_pix = (ii * 4) * DIMS + jj * 4;

    __shared__ __align__(16) float w_s[64][32];   // [k][o duplicated x2]
    __shared__ __align__(16) float p_s[64][64];   // [pos][b]

    int t = threadIdx.x;
    int to = t & 7;          // o0 = to*2
    int tb = t >> 3;         // b0 = tb*4
    int o0 = to * 2;
    int b0 = tb * 4;

    unsigned long long acc[2][2];  // [batch-pair][oi], lanes = (b, b+1)
    acc[0][0] = acc[0][1] = acc[1][0] = acc[1][1] = 0ull;

    for (int s = 0; s < 8; s++) {
        __syncthreads();
        // weights: vw[(((o*8)+s)*841 + p)*64 + k]; store duplicated [k][2o..2o+1]
        for (int f = t; f < 256; f += 128) {
            int o = f >> 4, kq = f & 15;
            float4 v = *(const float4*)&vw[((((o << 3) + s) * V4PIX) + p) * 64 + kq * 4];
            float2* d0 = (float2*)&w_s[kq * 4 + 0][o * 2];
            float2* d1 = (float2*)&w_s[kq * 4 + 1][o * 2];
            float2* d2 = (float2*)&w_s[kq * 4 + 2][o * 2];
            float2* d3 = (float2*)&w_s[kq * 4 + 3][o * 2];
            *d0 = make_float2(v.x, v.x);
            *d1 = make_float2(v.y, v.y);
            *d2 = make_float2(v.z, v.z);
            *d3 = make_float2(v.w, v.w);
        }
        // patch: cplx[s][base_pix + di*120 + dj][b], 64-float contiguous per pos
        const float* cb = g_cplx + s * (NPIX * B64);
        for (int f = t; f < 1024; f += 128) {
            int pos = f >> 4, bq = f & 15;
            int di = pos >> 3, dj = pos & 7;
            float4 v = *(const float4*)&cb[(base_pix + di * DIMS + dj) * B64 + bq * 4];
            *(float4*)&p_s[pos][bq * 4] = v;
        }
        __syncthreads();

#pragma unroll
        for (int k = 0; k < 64; k++) {
            ulonglong2 pv = *(const ulonglong2*)&p_s[k][b0];   // (b0,b0+1),(b0+2,b0+3)
            unsigned long long wv0 = *(const unsigned long long*)&w_s[k][o0 * 2];
            unsigned long long wv1 = *(const unsigned long long*)&w_s[k][(o0 + 1) * 2];
            fma_x2(acc[0][0], pv.x, wv0);
            fma_x2(acc[0][1], pv.x, wv1);
            fma_x2(acc[1][0], pv.y, wv0);
            fma_x2(acc[1][1], pv.y, wv1);
        }
    }

#pragma unroll
    for (int bp = 0; bp < 2; bp++)
#pragma unroll
        for (int oi = 0; oi < 2; oi++) {
            float2 f = *reinterpret_cast<float2*>(&acc[bp][oi]);
            int o = o0 + oi;
            g_v4[(b0 + bp * 2 + 0) * FLATN + o * V4PIX + p] = f.x;
            g_v4[(b0 + bp * 2 + 1) * FLATN + o * V4PIX + p] = f.y;
        }
}

// ---------------------------------------------------------------------------
// Kernel 3: decision readout. One block per batch element; deterministic
// fixed-order tree reduction.
// ---------------------------------------------------------------------------
__global__ __launch_bounds__(256)
void dec_kernel(const float* __restrict__ dw, const float* __restrict__ db,
                float* __restrict__ out)
{
    int b = blockIdx.x;
    int t = threadIdx.x;
    const float* v = g_v4 + b * FLATN;

    float a0 = 0.f, a1 = 0.f;
    for (int idx = t; idx < FLATN; idx += 256) {
        float vv = v[idx];
        a0 += vv * dw[idx];
        a1 += vv * dw[FLATN + idx];
    }

    __shared__ float s0[256], s1[256];
    s0[t] = a0; s1[t] = a1;
    __syncthreads();
    for (int off = 128; off > 0; off >>= 1) {
        if (t < off) { s0[t] += s0[t + off]; s1[t] += s1[t + off]; }
        __syncthreads();
    }
    if (t == 0) {
        out[b * 2 + 0] = s0[0] + db[0];
        out[b * 2 + 1] = s1[0] + db[1];
    }
}

// ---------------------------------------------------------------------------
extern "C" void kernel_launch(void* const* d_in, const int* in_sizes, int n_in,
                              void* d_out, int out_size)
{
    const float* x  = (const float*)d_in[0];   // [64,1,128,128]
    const float* sw = (const float*)d_in[1];   // [32,120,120,81]
    const float* vw = (const float*)d_in[2];   // [16,8,29,29,64]
    const float* dw = (const float*)d_in[3];   // [2,13456]
    const float* db = (const float*)d_in[4];   // [2]
    float* out = (float*)d_out;                // [64,2]

    v1_kernel<<<NPIX, 128>>>(x, sw);
    v4_kernel<<<V4PIX, 128>>>(vw);
    dec_kernel<<<B64, 256>>>(dw, db, out);
}

// round 3
// speedup vs baseline: 1.4587x; 1.2063x over previous
#include <cuda_runtime.h>

#define DIMS   120
#define NPIX   14400        // 120*120
#define SS2    81
#define C32    32
#define B64    64
#define PITCH  84           // 81 padded to 84 floats (21 quads); cols 81..83 zeroed
#define V4PIX  841          // 29*29
#define FLATN  13456        // 16*841
#define PPB    5            // pixels per v1 block (14400 = 2880 * 5)

// Intermediates (allocation-free scratch)
__device__ float g_cplx[8 * NPIX * B64];   // [s][pix][b]
__device__ float g_v4[B64 * FLATN];        // [b][o*841 + pix]

// packed fp32x2 FMA: d.lo += a.lo*b.lo, d.hi += a.hi*b.hi  (2x fp32 rate on sm_103a)
__device__ __forceinline__ void fma_x2(unsigned long long& d,
                                       unsigned long long a,
                                       unsigned long long b) {
    asm("fma.rn.f32x2 %0, %1, %2, %0;" : "+l"(d) : "l"(a), "l"(b));
}
__device__ __forceinline__ float hsum_x2(unsigned long long v) {
    float2 f = *reinterpret_cast<float2*>(&v);
    return f.x + f.y;
}

__device__ __forceinline__ void cp_async4(void* smem_dst, const void* gmem_src) {
    unsigned s = (unsigned)__cvta_generic_to_shared(smem_dst);
    asm volatile("cp.async.ca.shared.global [%0], [%1], 4;" :: "r"(s), "l"(gmem_src));
}
__device__ __forceinline__ void cp_commit() {
    asm volatile("cp.async.commit_group;");
}

// ---------------------------------------------------------------------------
// Kernel 1: V1 locally-connected layer + relu + phase-mean, fused.
// Persistent block handles PPB consecutive pixels; per-pixel weights are
// double-buffered via cp.async so DRAM latency overlaps the previous pixel's
// compute. Channel c lives at smem row (c>>2)+8*(c&3) (conflict-free LDS for
// thread tx reading rows tx+8*ci); batch row = b, thread reads ty+16*bi.
// ---------------------------------------------------------------------------
__global__ __launch_bounds__(128, 5)
void v1_kernel(const float* __restrict__ x, const float* __restrict__ w)
{
    __shared__ __align__(16) float w_s[2][C32][PITCH];
    __shared__ __align__(16) float p_s[B64][PITCH];

    int t  = threadIdx.x;
    int tx = t & 7;          // orientation s
    int ty = t >> 3;         // batch group
    int base = blockIdx.x * PPB;

    // zero the K padding (cols 81..83) once: 2*32 + 64 = 128 rows, one per thread
    {
        float* row;
        if (t < 64) row = &w_s[t >> 5][t & 31][0];
        else        row = &p_s[t - 64][0];
        row[81] = 0.f; row[82] = 0.f; row[83] = 0.f;
    }

    // prefetch weights for the first pixel into buffer 0
    {
        const float* wp = w + base * SS2;
        for (int idx = t; idx < C32 * SS2; idx += 128) {
            int c = idx / SS2;
            int k = idx - c * SS2;
            int row = (c >> 2) + ((c & 3) << 3);
            cp_async4(&w_s[0][row][k], wp + c * (NPIX * SS2) + k);
        }
        cp_commit();
    }

    for (int n = 0; n < PPB; n++) {
        int p = base + n;
        int i = p / DIMS;
        int j = p - i * DIMS;
        int buf = n & 1;

        // --- stage patches (L2-resident x): p_s[b][k] = x[b, i+k/9, j+k%9] ---
        const float* xp = x + i * 128 + j;
        for (int idx = t; idx < B64 * SS2; idx += 128) {
            int b = idx / SS2;
            int k = idx - b * SS2;
            int r = k / 9;
            int q = k - r * 9;
            p_s[b][k] = xp[b * 16384 + r * 128 + q];
        }

        // --- prefetch next pixel's weights into the other buffer ---
        if (n + 1 < PPB) {
            const float* wp = w + (p + 1) * SS2;
            for (int idx = t; idx < C32 * SS2; idx += 128) {
                int c = idx / SS2;
                int k = idx - c * SS2;
                int row = (c >> 2) + ((c & 3) << 3);
                cp_async4(&w_s[buf ^ 1][row][k], wp + c * (NPIX * SS2) + k);
            }
            cp_commit();
            asm volatile("cp.async.wait_group 1;");
        } else {
            asm volatile("cp.async.wait_group 0;");
        }
        __syncthreads();

        // --- register-tiled GEMM: thread = 4 batches x 4 channels ---
        unsigned long long acc[4][4];   // [bi][ci], fp32x2 lanes = (k even, k odd)
#pragma unroll
        for (int bi = 0; bi < 4; bi++)
#pragma unroll
            for (int ci = 0; ci < 4; ci++) acc[bi][ci] = 0ull;

        const float (*wb)[PITCH] = w_s[buf];

#pragma unroll 7
        for (int kq = 0; kq < 21; kq++) {
            ulonglong2 wv[4], pv[4];
#pragma unroll
            for (int ci = 0; ci < 4; ci++)
                wv[ci] = *(const ulonglong2*)&wb[tx + (ci << 3)][kq * 4];
#pragma unroll
            for (int bi = 0; bi < 4; bi++)
                pv[bi] = *(const ulonglong2*)&p_s[ty + (bi << 4)][kq * 4];
#pragma unroll
            for (int bi = 0; bi < 4; bi++)
#pragma unroll
                for (int ci = 0; ci < 4; ci++) {
                    fma_x2(acc[bi][ci], pv[bi].x, wv[ci].x);
                    fma_x2(acc[bi][ci], pv[bi].y, wv[ci].y);
                }
        }
        __syncthreads();   // everyone done reading w_s[buf] / p_s

        // --- relu + phase-mean into retired weight buffer: res[q=tx][b] ---
        float* resrow = &w_s[buf][tx][0];
#pragma unroll
        for (int bi = 0; bi < 4; bi++) {
            float s0 = fmaxf(hsum_x2(acc[bi][0]), 0.f);
            float s1 = fmaxf(hsum_x2(acc[bi][1]), 0.f);
            float s2 = fmaxf(hsum_x2(acc[bi][2]), 0.f);
            float s3 = fmaxf(hsum_x2(acc[bi][3]), 0.f);
            resrow[ty + (bi << 4)] = (s0 + s1 + s2 + s3) * 0.25f;
        }
        __syncthreads();

        // --- coalesced store: thread t writes plane q, 4 batches ---
        {
            int q  = t >> 4;
            int b4 = (t & 15) << 2;
            float4 v = *(const float4*)&w_s[buf][q][b4];
            *(float4*)&g_cplx[(q * NPIX + p) * B64 + b4] = v;
        }
        __syncthreads();   // guard w_s[buf] (refilled by next cp.async) & p_s
    }
}

// ---------------------------------------------------------------------------
// Kernel 2: V4 locally-connected pooling. One block per V4 pixel.
// out[b,o] = sum_{s,pos} cplx[s][pix2(pos)][b] * vw[o][s][pix][pos]
// fp32x2 lanes = adjacent batch pair; weight operand pre-duplicated in smem.
// ---------------------------------------------------------------------------
__global__ __launch_bounds__(128, 8)
void v4_kernel(const float* __restrict__ vw)
{
    int p = blockIdx.x;                 // 0..840
    int ii = p / 29;
    int jj = p - ii * 29;
    int base_pix = (ii * 4) * DIMS + jj * 4;

    __shared__ __align__(16) float w_s[64][32];   // [k][o duplicated x2]
    __shared__ __align__(16) float p_s[64][64];   // [pos][b]

    int t = threadIdx.x;
    int to = t & 7;          // o0 = to*2
    int tb = t >> 3;         // b0 = tb*4
    int o0 = to * 2;
    int b0 = tb * 4;

    unsigned long long acc[2][2];  // [batch-pair][oi], lanes = (b, b+1)
    acc[0][0] = acc[0][1] = acc[1][0] = acc[1][1] = 0ull;

    for (int s = 0; s < 8; s++) {
        __syncthreads();
        // weights: vw[(((o*8)+s)*841 + p)*64 + k]; store duplicated [k][2o..2o+1]
        for (int f = t; f < 256; f += 128) {
            int o = f >> 4, kq = f & 15;
            float4 v = *(const float4*)&vw[((((o << 3) + s) * V4PIX) + p) * 64 + kq * 4];
            *(float2*)&w_s[kq * 4 + 0][o * 2] = make_float2(v.x, v.x);
            *(float2*)&w_s[kq * 4 + 1][o * 2] = make_float2(v.y, v.y);
            *(float2*)&w_s[kq * 4 + 2][o * 2] = make_float2(v.z, v.z);
            *(float2*)&w_s[kq * 4 + 3][o * 2] = make_float2(v.w, v.w);
        }
        // patch: cplx[s][base_pix + di*120 + dj][b], 64-float contiguous per pos
        const float* cb = g_cplx + s * (NPIX * B64);
        for (int f = t; f < 1024; f += 128) {
            int pos = f >> 4, bq = f & 15;
            int di = pos >> 3, dj = pos & 7;
            float4 v = *(const float4*)&cb[(base_pix + di * DIMS + dj) * B64 + bq * 4];
            *(float4*)&p_s[pos][bq * 4] = v;
        }
        __syncthreads();

#pragma unroll
        for (int k = 0; k < 64; k++) {
            ulonglong2 pv = *(const ulonglong2*)&p_s[k][b0];   // (b0,b0+1),(b0+2,b0+3)
            unsigned long long wv0 = *(const unsigned long long*)&w_s[k][o0 * 2];
            unsigned long long wv1 = *(const unsigned long long*)&w_s[k][(o0 + 1) * 2];
            fma_x2(acc[0][0], pv.x, wv0);
            fma_x2(acc[0][1], pv.x, wv1);
            fma_x2(acc[1][0], pv.y, wv0);
            fma_x2(acc[1][1], pv.y, wv1);
        }
    }

#pragma unroll
    for (int bp = 0; bp < 2; bp++)
#pragma unroll
        for (int oi = 0; oi < 2; oi++) {
            float2 f = *reinterpret_cast<float2*>(&acc[bp][oi]);
            int o = o0 + oi;
            g_v4[(b0 + bp * 2 + 0) * FLATN + o * V4PIX + p] = f.x;
            g_v4[(b0 + bp * 2 + 1) * FLATN + o * V4PIX + p] = f.y;
        }
}

// ---------------------------------------------------------------------------
// Kernel 3: decision readout. One block per batch element; deterministic
// fixed-order tree reduction.
// ---------------------------------------------------------------------------
__global__ __launch_bounds__(256)
void dec_kernel(const float* __restrict__ dw, const float* __restrict__ db,
                float* __restrict__ out)
{
    int b = blockIdx.x;
    int t = threadIdx.x;
    const float* v = g_v4 + b * FLATN;

    float a0 = 0.f, a1 = 0.f;
    for (int idx = t; idx < FLATN; idx += 256) {
        float vv = v[idx];
        a0 += vv * dw[idx];
        a1 += vv * dw[FLATN + idx];
    }

    __shared__ float s0[256], s1[256];
    s0[t] = a0; s1[t] = a1;
    __syncthreads();
    for (int off = 128; off > 0; off >>= 1) {
        if (t < off) { s0[t] += s0[t + off]; s1[t] += s1[t + off]; }
        __syncthreads();
    }
    if (t == 0) {
        out[b * 2 + 0] = s0[0] + db[0];
        out[b * 2 + 1] = s1[0] + db[1];
    }
}

// ---------------------------------------------------------------------------
extern "C" void kernel_launch(void* const* d_in, const int* in_sizes, int n_in,
                              void* d_out, int out_size)
{
    const float* x  = (const float*)d_in[0];   // [64,1,128,128]
    const float* sw = (const float*)d_in[1];   // [32,120,120,81]
    const float* vw = (const float*)d_in[2];   // [16,8,29,29,64]
    const float* dw = (const float*)d_in[3];   // [2,13456]
    const float* db = (const float*)d_in[4];   // [2]
    float* out = (float*)d_out;                // [64,2]

    v1_kernel<<<NPIX / PPB, 128>>>(x, sw);
    v4_kernel<<<V4PIX, 128>>>(vw);
    dec_kernel<<<B64, 256>>>(dw, db, out);
}